// round 1
// baseline (speedup 1.0000x reference)
#include <cuda_runtime.h>
#include <cuda_bf16.h>

// Problem constants
#define BB 4
#define SS 4096
#define DD 128

// Scratch for Q,K,V projections (8 MB each) — __device__ globals, no allocation.
__device__ float g_Q[BB * SS * DD];
__device__ float g_K[BB * SS * DD];
__device__ float g_V[BB * SS * DD];

// ---------------------------------------------------------------------------
// Kernel 1: QKV projection.  y[i,e] = sum_d x[i,d] * W[e,d]   (x @ W^T)
// Grid: (128 row-blocks, 3 weights), 256 threads.
// smem: sX [128][128] (stride 128, reads are broadcast) + sW [128][129]
// ---------------------------------------------------------------------------
#define QKV_SMEM ((128 * 128 + 128 * 129) * 4)

__global__ void qkv_kernel(const float* __restrict__ x,
                           const float* __restrict__ Wq,
                           const float* __restrict__ Wk,
                           const float* __restrict__ Wv) {
    extern __shared__ float sm[];
    float* sX = sm;                 // [128][128]
    float* sW = sm + 128 * 128;     // [128][129]

    const int w = blockIdx.y;
    const float* W = (w == 0) ? Wq : (w == 1) ? Wk : Wv;
    float* out = (w == 0) ? g_Q : (w == 1) ? g_K : g_V;

    const int row0 = blockIdx.x * 128;
    const int tid = threadIdx.x;

    // Load x tile (contiguous float4 copy) and W (scalar stores, stride 129)
    for (int t = tid; t < 128 * 32; t += 256) {
        ((float4*)sX)[t] = ((const float4*)(x + (size_t)row0 * DD))[t];
        float4 wv = ((const float4*)W)[t];
        int off = t * 4;
        int r = off >> 7;
        int c = off & 127;
        float* dst = sW + r * 129 + c;
        dst[0] = wv.x; dst[1] = wv.y; dst[2] = wv.z; dst[3] = wv.w;
    }
    __syncthreads();

    const int ty = tid >> 4;
    const int tx = tid & 15;

    float acc[8][8];
#pragma unroll
    for (int i = 0; i < 8; i++)
#pragma unroll
        for (int j = 0; j < 8; j++) acc[i][j] = 0.0f;

    const float* xb = sX + (ty * 8) * 128;  // rows ty*8 .. ty*8+7 (broadcast reads)
    const float* wb = sW + tx * 129;        // cols tx + 16*j  (conflict-free)

#pragma unroll 4
    for (int d = 0; d < 128; d++) {
        float a[8], b[8];
#pragma unroll
        for (int i = 0; i < 8; i++) a[i] = xb[i * 128 + d];
#pragma unroll
        for (int j = 0; j < 8; j++) b[j] = wb[j * (16 * 129) + d];
#pragma unroll
        for (int i = 0; i < 8; i++)
#pragma unroll
            for (int j = 0; j < 8; j++) acc[i][j] += a[i] * b[j];
    }

#pragma unroll
    for (int i = 0; i < 8; i++) {
        int row = row0 + ty * 8 + i;
#pragma unroll
        for (int j = 0; j < 8; j++) {
            out[(size_t)row * DD + tx + 16 * j] = acc[i][j];
        }
    }
}

// ---------------------------------------------------------------------------
// Kernel 2: causal flash attention, fp32.
// Grid: (S/64 q-tiles [reversed: heavy first], B).  256 threads (16x16).
// Per-thread: 4 q-rows (ty*4+i), score cols tx+16j, O cols tx*8..tx*8+7.
// smem: sQ [64][128] | sK [64][129] (sP [64][68] overlaid) | sV [64][128]
// Total 98,560 B -> 2 CTAs/SM -> the full 256-CTA grid is one wave.
// ---------------------------------------------------------------------------
#define ATTN_SMEM ((64 * 128 + 64 * 129 + 64 * 128) * 4)

__device__ __forceinline__ float rowmax16(float v) {
    v = fmaxf(v, __shfl_xor_sync(0xffffffffu, v, 8));
    v = fmaxf(v, __shfl_xor_sync(0xffffffffu, v, 4));
    v = fmaxf(v, __shfl_xor_sync(0xffffffffu, v, 2));
    v = fmaxf(v, __shfl_xor_sync(0xffffffffu, v, 1));
    return v;
}
__device__ __forceinline__ float rowsum16(float v) {
    v += __shfl_xor_sync(0xffffffffu, v, 8);
    v += __shfl_xor_sync(0xffffffffu, v, 4);
    v += __shfl_xor_sync(0xffffffffu, v, 2);
    v += __shfl_xor_sync(0xffffffffu, v, 1);
    return v;
}

__global__ void attn_kernel(float* __restrict__ out) {
    extern __shared__ float sm[];
    float* sQ = sm;                   // [64][128], reads broadcast
    float* sK = sm + 64 * 128;        // [64][129], conflict-free scalar reads
    float* sP = sK;                   // overlay: [64][68] (fits in sK's 64*129)
    float* sV = sK + 64 * 129;        // [64][128], contiguous float4 reads

    const int iq = (gridDim.x - 1) - blockIdx.x;  // heavy q-tiles first
    const int b = blockIdx.y;

    const float* Qg = g_Q + (size_t)b * SS * DD + (size_t)iq * 64 * DD;
    const float* Kg = g_K + (size_t)b * SS * DD;
    const float* Vg = g_V + (size_t)b * SS * DD;

    const int tid = threadIdx.x;
    const int ty = tid >> 4;
    const int tx = tid & 15;

    // Load Q tile once (contiguous)
    for (int t = tid; t < 64 * 32; t += 256) {
        ((float4*)sQ)[t] = ((const float4*)Qg)[t];
    }

    float m_[4], l_[4], o_[4][8];
#pragma unroll
    for (int i = 0; i < 4; i++) {
        m_[i] = -1e30f;
        l_[i] = 0.0f;
#pragma unroll
        for (int c = 0; c < 8; c++) o_[i][c] = 0.0f;
    }

    const float scale = 0.08838834764831845f;  // 1/sqrt(128)

    for (int jt = 0; jt <= iq; jt++) {
        __syncthreads();  // prev PV done (sV, sP) before overwriting sK/sV

        // Load K (scalar stores, stride 129) and V (float4, stride 128)
        const float* Kt = Kg + (size_t)jt * 64 * DD;
        const float* Vt = Vg + (size_t)jt * 64 * DD;
        for (int t = tid; t < 2048; t += 256) {
            float4 kv = ((const float4*)Kt)[t];
            int off = t * 4;
            int r = off >> 7;
            int c = off & 127;
            float* dst = sK + r * 129 + c;
            dst[0] = kv.x; dst[1] = kv.y; dst[2] = kv.z; dst[3] = kv.w;
            ((float4*)sV)[t] = ((const float4*)Vt)[t];
        }
        __syncthreads();

        // ---- scores: acc[i][j] = q(row ty*4+i) . k(col tx+16j) ----
        float acc[4][4];
#pragma unroll
        for (int i = 0; i < 4; i++)
#pragma unroll
            for (int j = 0; j < 4; j++) acc[i][j] = 0.0f;

        const float* qb = sQ + (ty * 4) * 128;
        const float* kb = sK + tx * 129;

#pragma unroll 8
        for (int d = 0; d < 128; d++) {
            float a0 = qb[d], a1 = qb[128 + d], a2 = qb[256 + d], a3 = qb[384 + d];
            float b0 = kb[d], b1 = kb[2064 + d], b2 = kb[4128 + d], b3 = kb[6192 + d];
            acc[0][0] += a0 * b0; acc[0][1] += a0 * b1; acc[0][2] += a0 * b2; acc[0][3] += a0 * b3;
            acc[1][0] += a1 * b0; acc[1][1] += a1 * b1; acc[1][2] += a1 * b2; acc[1][3] += a1 * b3;
            acc[2][0] += a2 * b0; acc[2][1] += a2 * b1; acc[2][2] += a2 * b2; acc[2][3] += a2 * b3;
            acc[3][0] += a3 * b0; acc[3][1] += a3 * b1; acc[3][2] += a3 * b2; acc[3][3] += a3 * b3;
        }

        // scale + causal mask (only the diagonal tile needs masking)
        const bool diag = (jt == iq);
#pragma unroll
        for (int i = 0; i < 4; i++) {
            int qr = iq * 64 + ty * 4 + i;
#pragma unroll
            for (int j = 0; j < 4; j++) {
                float s = acc[i][j] * scale;
                if (diag) {
                    int kc = jt * 64 + tx + 16 * j;
                    if (kc > qr) s = -1e30f;
                }
                acc[i][j] = s;
            }
        }

        // ---- online softmax (per row, reduced across the 16 tx lanes) ----
#pragma unroll
        for (int i = 0; i < 4; i++) {
            float mx = fmaxf(fmaxf(acc[i][0], acc[i][1]), fmaxf(acc[i][2], acc[i][3]));
            mx = rowmax16(mx);
            float nm = fmaxf(m_[i], mx);
            float fac = __expf(m_[i] - nm);
            float rs = 0.0f;
#pragma unroll
            for (int j = 0; j < 4; j++) {
                acc[i][j] = __expf(acc[i][j] - nm);
                rs += acc[i][j];
            }
            rs = rowsum16(rs);
            l_[i] = l_[i] * fac + rs;
            m_[i] = nm;
#pragma unroll
            for (int c = 0; c < 8; c++) o_[i][c] *= fac;
        }

        __syncthreads();  // all score reads of sK done before sP overlay write

        // store P to shared (stride 68: the two ty-halves of a warp hit
        // disjoint bank halves -> conflict-free)
#pragma unroll
        for (int i = 0; i < 4; i++)
#pragma unroll
            for (int j = 0; j < 4; j++)
                sP[(ty * 4 + i) * 68 + tx + 16 * j] = acc[i][j];

        __syncthreads();

        // ---- PV: o[i][c] += sum_k P[row, k] * V[k, tx*8+c] ----
        const float* pb = sP + (ty * 4) * 68;
        const float* vb = sV + tx * 8;
#pragma unroll 4
        for (int k = 0; k < 64; k++) {
            float p0 = pb[k], p1 = pb[68 + k], p2 = pb[136 + k], p3 = pb[204 + k];
            float4 v0 = *(const float4*)(vb + k * 128);
            float4 v1 = *(const float4*)(vb + k * 128 + 4);
            o_[0][0] += p0 * v0.x; o_[0][1] += p0 * v0.y; o_[0][2] += p0 * v0.z; o_[0][3] += p0 * v0.w;
            o_[0][4] += p0 * v1.x; o_[0][5] += p0 * v1.y; o_[0][6] += p0 * v1.z; o_[0][7] += p0 * v1.w;
            o_[1][0] += p1 * v0.x; o_[1][1] += p1 * v0.y; o_[1][2] += p1 * v0.z; o_[1][3] += p1 * v0.w;
            o_[1][4] += p1 * v1.x; o_[1][5] += p1 * v1.y; o_[1][6] += p1 * v1.z; o_[1][7] += p1 * v1.w;
            o_[2][0] += p2 * v0.x; o_[2][1] += p2 * v0.y; o_[2][2] += p2 * v0.z; o_[2][3] += p2 * v0.w;
            o_[2][4] += p2 * v1.x; o_[2][5] += p2 * v1.y; o_[2][6] += p2 * v1.z; o_[2][7] += p2 * v1.w;
            o_[3][0] += p3 * v0.x; o_[3][1] += p3 * v0.y; o_[3][2] += p3 * v0.z; o_[3][3] += p3 * v0.w;
            o_[3][4] += p3 * v1.x; o_[3][5] += p3 * v1.y; o_[3][6] += p3 * v1.z; o_[3][7] += p3 * v1.w;
        }
    }

    // Epilogue: normalize and write out (float4, coalesced over tx)
#pragma unroll
    for (int i = 0; i < 4; i++) {
        float inv = 1.0f / l_[i];
        int row = iq * 64 + ty * 4 + i;
        float* dst = out + ((size_t)b * SS + row) * DD + tx * 8;
        float4 r0, r1;
        r0.x = o_[i][0] * inv; r0.y = o_[i][1] * inv;
        r0.z = o_[i][2] * inv; r0.w = o_[i][3] * inv;
        r1.x = o_[i][4] * inv; r1.y = o_[i][5] * inv;
        r1.z = o_[i][6] * inv; r1.w = o_[i][7] * inv;
        *(float4*)dst = r0;
        *(float4*)(dst + 4) = r1;
    }
}

// ---------------------------------------------------------------------------
extern "C" void kernel_launch(void* const* d_in, const int* in_sizes, int n_in,
                              void* d_out, int out_size) {
    const float* x  = (const float*)d_in[0];
    const float* Wq = (const float*)d_in[1];
    const float* Wk = (const float*)d_in[2];
    const float* Wv = (const float*)d_in[3];
    float* out = (float*)d_out;

    // Opt into >48KB dynamic smem (idempotent; not a stream op, capture-safe).
    cudaFuncSetAttribute(qkv_kernel, cudaFuncAttributeMaxDynamicSharedMemorySize, QKV_SMEM);
    cudaFuncSetAttribute(attn_kernel, cudaFuncAttributeMaxDynamicSharedMemorySize, ATTN_SMEM);

    qkv_kernel<<<dim3(BB * SS / 128, 3), 256, QKV_SMEM>>>(x, Wq, Wk, Wv);
    attn_kernel<<<dim3(SS / 64, BB), 256, ATTN_SMEM>>>(out);
}

// round 2
// speedup vs baseline: 3.8273x; 3.8273x over previous
#include <cuda_runtime.h>
#include <cuda_bf16.h>
#include <cstdint>

// Problem constants
#define BB 4
#define SS 4096
#define DD 128

// bf16 hi/lo split Q,K,V (scale folded into Q). 4 MB each.
__device__ __nv_bfloat16 g_Qh[BB * SS * DD];
__device__ __nv_bfloat16 g_Ql[BB * SS * DD];
__device__ __nv_bfloat16 g_Kh[BB * SS * DD];
__device__ __nv_bfloat16 g_Kl[BB * SS * DD];
__device__ __nv_bfloat16 g_Vh[BB * SS * DD];
__device__ __nv_bfloat16 g_Vl[BB * SS * DD];

// ---------------------------------------------------------------------------
// Kernel 1: QKV projection (fp32 FMA), output split into bf16 hi + lo.
//   y = x @ W^T ;  Q additionally scaled by 1/sqrt(128).
// ---------------------------------------------------------------------------
#define QKV_SMEM ((128 * 128 + 128 * 129) * 4)

__global__ void qkv_kernel(const float* __restrict__ x,
                           const float* __restrict__ Wq,
                           const float* __restrict__ Wk,
                           const float* __restrict__ Wv) {
    extern __shared__ float sm[];
    float* sX = sm;                 // [128][128]
    float* sW = sm + 128 * 128;     // [128][129]

    const int w = blockIdx.y;
    const float* W = (w == 0) ? Wq : (w == 1) ? Wk : Wv;
    __nv_bfloat16* oh = (w == 0) ? g_Qh : (w == 1) ? g_Kh : g_Vh;
    __nv_bfloat16* ol = (w == 0) ? g_Ql : (w == 1) ? g_Kl : g_Vl;
    const float sc = (w == 0) ? 0.08838834764831845f : 1.0f;

    const int row0 = blockIdx.x * 128;
    const int tid = threadIdx.x;

    for (int t = tid; t < 128 * 32; t += 256) {
        ((float4*)sX)[t] = ((const float4*)(x + (size_t)row0 * DD))[t];
        float4 wv = ((const float4*)W)[t];
        int off = t * 4;
        int r = off >> 7;
        int c = off & 127;
        float* dst = sW + r * 129 + c;
        dst[0] = wv.x; dst[1] = wv.y; dst[2] = wv.z; dst[3] = wv.w;
    }
    __syncthreads();

    const int ty = tid >> 4;
    const int tx = tid & 15;

    float acc[8][8];
#pragma unroll
    for (int i = 0; i < 8; i++)
#pragma unroll
        for (int j = 0; j < 8; j++) acc[i][j] = 0.0f;

    const float* xb = sX + (ty * 8) * 128;
    const float* wb = sW + tx * 129;

#pragma unroll 4
    for (int d = 0; d < 128; d++) {
        float a[8], b[8];
#pragma unroll
        for (int i = 0; i < 8; i++) a[i] = xb[i * 128 + d];
#pragma unroll
        for (int j = 0; j < 8; j++) b[j] = wb[j * (16 * 129) + d];
#pragma unroll
        for (int i = 0; i < 8; i++)
#pragma unroll
            for (int j = 0; j < 8; j++) acc[i][j] += a[i] * b[j];
    }

#pragma unroll
    for (int i = 0; i < 8; i++) {
        size_t row = row0 + ty * 8 + i;
#pragma unroll
        for (int j = 0; j < 8; j++) {
            float y = acc[i][j] * sc;
            __nv_bfloat16 h = __float2bfloat16(y);
            float hf = __bfloat162float(h);
            __nv_bfloat16 l = __float2bfloat16(y - hf);
            oh[row * DD + tx + 16 * j] = h;
            ol[row * DD + tx + 16 * j] = l;
        }
    }
}

// ---------------------------------------------------------------------------
// Kernel 2: causal flash attention via mma.sync bf16 with 2-way splitting.
//
// CTA: 128 threads = 4 warps; q-tile 64 rows (warp w owns rows w*16..w*16+15);
// k-tile 64 keys. CTA x processes q-tiles {x, 63-x}: exactly 65 iterations
// for every CTA -> perfectly balanced single wave of 128 CTAs.
//
// smem (bf16, row stride 136 halves = 272 B; 272 % 128 == 16 so the 8 row
// pointers of any ldmatrix phase land on distinct 16B bank groups):
//   Qh,Ql,Kh,Kl,Vh,Vl tiles of 64 x 136 halves -> 6 * 17408 = 104448 B.
//
// Fragment maps (m16n8k16, row.col):
//   A (Q / P):  a0={r,2c},{r,2c+1}  a1={r+8,..}  a2={r,2c+8..}  a3={r+8,2c+8..}
//               via ldmatrix.x4 non-trans on row-major [m][k].
//   B (K):  b0={k=2c, n=r}, b1={k=2c+8, n=r}; K stored [key=n][d=k] row-major
//               == col-major B -> ldmatrix.x2 non-trans, lanes 0-7 matrix {n0..7,k0..7},
//               lanes 8-15 {n0..7, k8..15}.
//   B (V):  contraction k = key; V stored [key][d] row-major == row-major B ->
//               ldmatrix.x2.trans, lanes 0-7 rows key 0..7, 8-15 rows key 8..15.
//   C:      c0={r,2c} c1={r,2c+1} c2={r+8,2c} c3={r+8,2c+1}  (r=lane/4, c=lane%4)
//   S-accum C tiles reused directly as PV A fragments (FA2 trick):
//   kp-th PV k16 = S n-tiles {2kp, 2kp+1}: a0=pack(c[2kp][0],c[2kp][1]),
//   a1=pack(c[2kp][2],c[2kp][3]), a2/a3 same on n-tile 2kp+1.
// ---------------------------------------------------------------------------
#define T_HALF 8704                      // 64 * 136 halves per tile
#define ATTN_SMEM (6 * T_HALF * 2)       // 104448 B

__device__ __forceinline__ void ldsm_x4(uint32_t r[4], uint32_t addr) {
    asm volatile("ldmatrix.sync.aligned.m8n8.x4.shared.b16 {%0,%1,%2,%3}, [%4];"
                 : "=r"(r[0]), "=r"(r[1]), "=r"(r[2]), "=r"(r[3]) : "r"(addr));
}
__device__ __forceinline__ void ldsm_x2(uint32_t r[2], uint32_t addr) {
    asm volatile("ldmatrix.sync.aligned.m8n8.x2.shared.b16 {%0,%1}, [%2];"
                 : "=r"(r[0]), "=r"(r[1]) : "r"(addr));
}
__device__ __forceinline__ void ldsm_x2t(uint32_t r[2], uint32_t addr) {
    asm volatile("ldmatrix.sync.aligned.m8n8.x2.trans.shared.b16 {%0,%1}, [%2];"
                 : "=r"(r[0]), "=r"(r[1]) : "r"(addr));
}
__device__ __forceinline__ void mma_bf16(float c[4], const uint32_t a[4],
                                         const uint32_t b[2]) {
    asm volatile(
        "mma.sync.aligned.m16n8k16.row.col.f32.bf16.bf16.f32 "
        "{%0,%1,%2,%3}, {%4,%5,%6,%7}, {%8,%9}, {%0,%1,%2,%3};"
        : "+f"(c[0]), "+f"(c[1]), "+f"(c[2]), "+f"(c[3])
        : "r"(a[0]), "r"(a[1]), "r"(a[2]), "r"(a[3]), "r"(b[0]), "r"(b[1]));
}
// pack (x0,x1) -> bf16x2 hi-part, and residual lo-part (x - float(hi))
__device__ __forceinline__ void split_pack(float x0, float x1,
                                           uint32_t& hp, uint32_t& lp) {
    asm("cvt.rn.bf16x2.f32 %0, %1, %2;" : "=r"(hp) : "f"(x1), "f"(x0));
    float h0 = __uint_as_float(hp << 16);
    float h1 = __uint_as_float(hp & 0xffff0000u);
    asm("cvt.rn.bf16x2.f32 %0, %1, %2;" : "=r"(lp) : "f"(x1 - h1), "f"(x0 - h0));
}

__global__ __launch_bounds__(128) void attn_kernel(float* __restrict__ out) {
    extern __shared__ __nv_bfloat16 smh[];
    __nv_bfloat16* sQh = smh;
    __nv_bfloat16* sQl = smh + T_HALF;
    __nv_bfloat16* sKh = smh + 2 * T_HALF;
    __nv_bfloat16* sKl = smh + 3 * T_HALF;
    __nv_bfloat16* sVh = smh + 4 * T_HALF;
    __nv_bfloat16* sVl = smh + 5 * T_HALF;

    const uint32_t uB  = (uint32_t)__cvta_generic_to_shared(smh);
    const uint32_t uQh = uB;
    const uint32_t uQl = uB + T_HALF * 2;
    const uint32_t uKh = uB + 2 * T_HALF * 2;
    const uint32_t uKl = uB + 3 * T_HALF * 2;
    const uint32_t uVh = uB + 4 * T_HALF * 2;
    const uint32_t uVl = uB + 5 * T_HALF * 2;

    const int b = blockIdx.y;
    const int tid = threadIdx.x;
    const int warp = tid >> 5;
    const int lane = tid & 31;

    // per-lane ldmatrix byte offsets
    const uint32_t qoff = (uint32_t)(((warp * 16 + (lane & 15)) * 136 +
                                      ((lane >> 4) << 3)) * 2);
    const uint32_t koff = (uint32_t)(((lane & 7) * 136 +
                                      (((lane >> 3) & 1) << 3)) * 2);
    const uint32_t voff = (uint32_t)((lane & 15) * 136 * 2);

    const float NEG = -1e30f;

    for (int pass = 0; pass < 2; pass++) {
        const int iq = pass ? (63 - blockIdx.x) : blockIdx.x;
        __syncthreads();  // smem (Q) free from previous pass

        // load Q tile (hi/lo), 8 uint4 per thread per tile
        {
            const uint4* QH = (const uint4*)(g_Qh + ((size_t)b * SS + iq * 64) * DD);
            const uint4* QL = (const uint4*)(g_Ql + ((size_t)b * SS + iq * 64) * DD);
#pragma unroll
            for (int i = 0; i < 8; i++) {
                int idx = tid + i * 128;
                int r = idx >> 4, c = idx & 15;
                *(uint4*)(sQh + r * 136 + c * 8) = QH[idx];
                *(uint4*)(sQl + r * 136 + c * 8) = QL[idx];
            }
        }

        float o[16][4];
#pragma unroll
        for (int nd = 0; nd < 16; nd++)
#pragma unroll
            for (int k = 0; k < 4; k++) o[nd][k] = 0.0f;
        float mr0 = NEG, mr1 = NEG, lr0 = 0.0f, lr1 = 0.0f;

        for (int jt = 0; jt <= iq; jt++) {
            __syncthreads();  // previous iter's K/V reads done
            {
                const size_t goff = ((size_t)b * SS + jt * 64) * DD;
                const uint4* KH = (const uint4*)(g_Kh + goff);
                const uint4* KL = (const uint4*)(g_Kl + goff);
                const uint4* VH = (const uint4*)(g_Vh + goff);
                const uint4* VL = (const uint4*)(g_Vl + goff);
#pragma unroll
                for (int i = 0; i < 8; i++) {
                    int idx = tid + i * 128;
                    int r = idx >> 4, c = idx & 15;
                    *(uint4*)(sKh + r * 136 + c * 8) = KH[idx];
                    *(uint4*)(sKl + r * 136 + c * 8) = KL[idx];
                    *(uint4*)(sVh + r * 136 + c * 8) = VH[idx];
                    *(uint4*)(sVl + r * 136 + c * 8) = VL[idx];
                }
            }
            __syncthreads();

            // ---- S = Q K^T (scale pre-folded into Q) ----
            float c_[8][4];
#pragma unroll
            for (int nt = 0; nt < 8; nt++)
#pragma unroll
                for (int k = 0; k < 4; k++) c_[nt][k] = 0.0f;

            for (int ks = 0; ks < 8; ks++) {  // k-steps of 16 over d=128
                uint32_t qa[4], ql[4];
                ldsm_x4(qa, uQh + qoff + ks * 32);
                ldsm_x4(ql, uQl + qoff + ks * 32);
#pragma unroll
                for (int nt = 0; nt < 8; nt++) {
                    uint32_t kh[2], kl[2];
                    uint32_t off = koff + (uint32_t)((nt * 8 * 136 + ks * 16) * 2);
                    ldsm_x2(kh, uKh + off);
                    ldsm_x2(kl, uKl + off);
                    mma_bf16(c_[nt], qa, kh);
                    mma_bf16(c_[nt], qa, kl);
                    mma_bf16(c_[nt], ql, kh);
                }
            }

            // ---- causal mask (diagonal tile only) ----
            if (jt == iq) {
                const int rl0 = warp * 16 + (lane >> 2);
                const int rl1 = rl0 + 8;
#pragma unroll
                for (int nt = 0; nt < 8; nt++) {
                    int cl = nt * 8 + (lane & 3) * 2;
                    if (cl > rl0) c_[nt][0] = NEG;
                    if (cl + 1 > rl0) c_[nt][1] = NEG;
                    if (cl > rl1) c_[nt][2] = NEG;
                    if (cl + 1 > rl1) c_[nt][3] = NEG;
                }
            }

            // ---- online softmax (rows r0 = lane/4, r1 = r0+8) ----
            float mx0 = NEG, mx1 = NEG;
#pragma unroll
            for (int nt = 0; nt < 8; nt++) {
                mx0 = fmaxf(mx0, fmaxf(c_[nt][0], c_[nt][1]));
                mx1 = fmaxf(mx1, fmaxf(c_[nt][2], c_[nt][3]));
            }
            mx0 = fmaxf(mx0, __shfl_xor_sync(0xffffffffu, mx0, 1));
            mx0 = fmaxf(mx0, __shfl_xor_sync(0xffffffffu, mx0, 2));
            mx1 = fmaxf(mx1, __shfl_xor_sync(0xffffffffu, mx1, 1));
            mx1 = fmaxf(mx1, __shfl_xor_sync(0xffffffffu, mx1, 2));

            float nm0 = fmaxf(mr0, mx0), nm1 = fmaxf(mr1, mx1);
            float f0 = __expf(mr0 - nm0), f1 = __expf(mr1 - nm1);
            mr0 = nm0; mr1 = nm1;

            float rs0 = 0.0f, rs1 = 0.0f;
#pragma unroll
            for (int nt = 0; nt < 8; nt++) {
                c_[nt][0] = __expf(c_[nt][0] - nm0);
                c_[nt][1] = __expf(c_[nt][1] - nm0);
                c_[nt][2] = __expf(c_[nt][2] - nm1);
                c_[nt][3] = __expf(c_[nt][3] - nm1);
                rs0 += c_[nt][0] + c_[nt][1];
                rs1 += c_[nt][2] + c_[nt][3];
            }
            rs0 += __shfl_xor_sync(0xffffffffu, rs0, 1);
            rs0 += __shfl_xor_sync(0xffffffffu, rs0, 2);
            rs1 += __shfl_xor_sync(0xffffffffu, rs1, 1);
            rs1 += __shfl_xor_sync(0xffffffffu, rs1, 2);
            lr0 = lr0 * f0 + rs0;
            lr1 = lr1 * f1 + rs1;

#pragma unroll
            for (int nd = 0; nd < 16; nd++) {
                o[nd][0] *= f0; o[nd][1] *= f0;
                o[nd][2] *= f1; o[nd][3] *= f1;
            }

            // ---- O += P V  (P split into hi/lo on the fly) ----
#pragma unroll
            for (int kp = 0; kp < 4; kp++) {
                uint32_t ph[4], pl[4];
                split_pack(c_[2 * kp][0],     c_[2 * kp][1],     ph[0], pl[0]);
                split_pack(c_[2 * kp][2],     c_[2 * kp][3],     ph[1], pl[1]);
                split_pack(c_[2 * kp + 1][0], c_[2 * kp + 1][1], ph[2], pl[2]);
                split_pack(c_[2 * kp + 1][2], c_[2 * kp + 1][3], ph[3], pl[3]);
#pragma unroll
                for (int nd = 0; nd < 16; nd++) {
                    uint32_t vh[2], vl[2];
                    uint32_t off = voff + (uint32_t)((kp * 16 * 136 + nd * 8) * 2);
                    ldsm_x2t(vh, uVh + off);
                    ldsm_x2t(vl, uVl + off);
                    mma_bf16(o[nd], ph, vh);
                    mma_bf16(o[nd], ph, vl);
                    mma_bf16(o[nd], pl, vh);
                }
            }
        }

        // ---- epilogue ----
        const float i0 = 1.0f / lr0, i1 = 1.0f / lr1;
        const int r0g = iq * 64 + warp * 16 + (lane >> 2);
        const int r1g = r0g + 8;
        float* o0 = out + ((size_t)b * SS + r0g) * DD + (lane & 3) * 2;
        float* o1 = out + ((size_t)b * SS + r1g) * DD + (lane & 3) * 2;
#pragma unroll
        for (int nd = 0; nd < 16; nd++) {
            *(float2*)(o0 + nd * 8) = make_float2(o[nd][0] * i0, o[nd][1] * i0);
            *(float2*)(o1 + nd * 8) = make_float2(o[nd][2] * i1, o[nd][3] * i1);
        }
    }
}

// ---------------------------------------------------------------------------
extern "C" void kernel_launch(void* const* d_in, const int* in_sizes, int n_in,
                              void* d_out, int out_size) {
    const float* x  = (const float*)d_in[0];
    const float* Wq = (const float*)d_in[1];
    const float* Wk = (const float*)d_in[2];
    const float* Wv = (const float*)d_in[3];
    float* out = (float*)d_out;

    cudaFuncSetAttribute(qkv_kernel, cudaFuncAttributeMaxDynamicSharedMemorySize, QKV_SMEM);
    cudaFuncSetAttribute(attn_kernel, cudaFuncAttributeMaxDynamicSharedMemorySize, ATTN_SMEM);

    qkv_kernel<<<dim3(BB * SS / 128, 3), 256, QKV_SMEM>>>(x, Wq, Wk, Wv);
    attn_kernel<<<dim3(32, BB), 128, ATTN_SMEM>>>(out);
}

// round 4
// speedup vs baseline: 4.3209x; 1.1290x over previous
#include <cuda_runtime.h>
#include <cuda_bf16.h>
#include <cstdint>

// Problem constants
#define BB 4
#define SS 4096
#define DD 128

// bf16 hi/lo split Q,K,V (scale folded into Q). 4 MB each.
__device__ __nv_bfloat16 g_Qh[BB * SS * DD];
__device__ __nv_bfloat16 g_Ql[BB * SS * DD];
__device__ __nv_bfloat16 g_Kh[BB * SS * DD];
__device__ __nv_bfloat16 g_Kl[BB * SS * DD];
__device__ __nv_bfloat16 g_Vh[BB * SS * DD];
__device__ __nv_bfloat16 g_Vl[BB * SS * DD];

// ---------------------------------------------------------------------------
// Kernel 1: QKV projection (fp32 FMA), output split into bf16 hi + lo.
// ---------------------------------------------------------------------------
#define QKV_SMEM ((128 * 128 + 128 * 129) * 4)

__global__ void qkv_kernel(const float* __restrict__ x,
                           const float* __restrict__ Wq,
                           const float* __restrict__ Wk,
                           const float* __restrict__ Wv) {
    extern __shared__ float sm[];
    float* sX = sm;
    float* sW = sm + 128 * 128;

    const int w = blockIdx.y;
    const float* W = (w == 0) ? Wq : (w == 1) ? Wk : Wv;
    __nv_bfloat16* oh = (w == 0) ? g_Qh : (w == 1) ? g_Kh : g_Vh;
    __nv_bfloat16* ol = (w == 0) ? g_Ql : (w == 1) ? g_Kl : g_Vl;
    const float sc = (w == 0) ? 0.08838834764831845f : 1.0f;

    const int row0 = blockIdx.x * 128;
    const int tid = threadIdx.x;

    for (int t = tid; t < 128 * 32; t += 256) {
        ((float4*)sX)[t] = ((const float4*)(x + (size_t)row0 * DD))[t];
        float4 wv = ((const float4*)W)[t];
        int off = t * 4;
        int r = off >> 7;
        int c = off & 127;
        float* dst = sW + r * 129 + c;
        dst[0] = wv.x; dst[1] = wv.y; dst[2] = wv.z; dst[3] = wv.w;
    }
    __syncthreads();

    const int ty = tid >> 4;
    const int tx = tid & 15;

    float acc[8][8];
#pragma unroll
    for (int i = 0; i < 8; i++)
#pragma unroll
        for (int j = 0; j < 8; j++) acc[i][j] = 0.0f;

    const float* xb = sX + (ty * 8) * 128;
    const float* wb = sW + tx * 129;

#pragma unroll 4
    for (int d = 0; d < 128; d++) {
        float a[8], b[8];
#pragma unroll
        for (int i = 0; i < 8; i++) a[i] = xb[i * 128 + d];
#pragma unroll
        for (int j = 0; j < 8; j++) b[j] = wb[j * (16 * 129) + d];
#pragma unroll
        for (int i = 0; i < 8; i++)
#pragma unroll
            for (int j = 0; j < 8; j++) acc[i][j] += a[i] * b[j];
    }

#pragma unroll
    for (int i = 0; i < 8; i++) {
        size_t row = row0 + ty * 8 + i;
#pragma unroll
        for (int j = 0; j < 8; j++) {
            float y = acc[i][j] * sc;
            __nv_bfloat16 h = __float2bfloat16(y);
            float hf = __bfloat162float(h);
            __nv_bfloat16 l = __float2bfloat16(y - hf);
            oh[row * DD + tx + 16 * j] = h;
            ol[row * DD + tx + 16 * j] = l;
        }
    }
}

// ---------------------------------------------------------------------------
// Kernel 2: causal flash attention, mma.sync bf16 2-way split, 8 warps/CTA.
// Warp w: q-row group wg=w&3 (rows wg*16..+15), key half h=w>>2.
// Independent online softmax per key half; merged once per pass via smem.
// CTA x -> q-tiles {x, 63-x}: 65 iterations per CTA, 128 CTAs, one wave.
// K/V double-buffered via cp.async. hi/lo ldmatrix fused (lanes 16-31 -> lo).
// ---------------------------------------------------------------------------
#define T_HALF 8704
#define ATTN_SMEM (10 * T_HALF * 2)      // 174080 B

__device__ __forceinline__ void ldsm_x4(uint32_t r[4], uint32_t addr) {
    asm volatile("ldmatrix.sync.aligned.m8n8.x4.shared.b16 {%0,%1,%2,%3}, [%4];"
                 : "=r"(r[0]), "=r"(r[1]), "=r"(r[2]), "=r"(r[3]) : "r"(addr));
}
__device__ __forceinline__ void ldsm_x4t(uint32_t r[4], uint32_t addr) {
    asm volatile("ldmatrix.sync.aligned.m8n8.x4.trans.shared.b16 {%0,%1,%2,%3}, [%4];"
                 : "=r"(r[0]), "=r"(r[1]), "=r"(r[2]), "=r"(r[3]) : "r"(addr));
}
__device__ __forceinline__ void mma_bf16(float c[4], const uint32_t a[4],
                                         const uint32_t b[2]) {
    asm volatile(
        "mma.sync.aligned.m16n8k16.row.col.f32.bf16.bf16.f32 "
        "{%0,%1,%2,%3}, {%4,%5,%6,%7}, {%8,%9}, {%0,%1,%2,%3};"
        : "+f"(c[0]), "+f"(c[1]), "+f"(c[2]), "+f"(c[3])
        : "r"(a[0]), "r"(a[1]), "r"(a[2]), "r"(a[3]), "r"(b[0]), "r"(b[1]));
}
__device__ __forceinline__ void split_pack(float x0, float x1,
                                           uint32_t& hp, uint32_t& lp) {
    asm("cvt.rn.bf16x2.f32 %0, %1, %2;" : "=r"(hp) : "f"(x1), "f"(x0));
    float h0 = __uint_as_float(hp << 16);
    float h1 = __uint_as_float(hp & 0xffff0000u);
    asm("cvt.rn.bf16x2.f32 %0, %1, %2;" : "=r"(lp) : "f"(x1 - h1), "f"(x0 - h0));
}
__device__ __forceinline__ void cp16(uint32_t dst, const void* src) {
    asm volatile("cp.async.cg.shared.global [%0], [%1], 16;" :: "r"(dst), "l"(src));
}

__global__ __launch_bounds__(256, 1) void attn_kernel(float* __restrict__ out) {
    extern __shared__ __nv_bfloat16 smh[];

    const uint32_t uB  = (uint32_t)__cvta_generic_to_shared(smh);
    const uint32_t uQh = uB;
    const uint32_t uQl = uB + T_HALF * 2;
    const uint32_t uKV = uB + 2 * T_HALF * 2;      // stage s at uKV + s*4T*2

    __nv_bfloat16* sQh = smh;
    __nv_bfloat16* sQl = smh + T_HALF;
    // epilogue merge buffers overlay KV stage 1
    float* OB = (float*)(smh + 6 * T_HALF);        // [64][132]
    float* mB = OB + 64 * 132;
    float* lB = mB + 64;

    const int b = blockIdx.y;
    const int tid = threadIdx.x;
    const int warp = tid >> 5;
    const int lane = tid & 31;
    const int wg = warp & 3;          // q-row group
    const int h = warp >> 2;          // key half (0: keys 0-31, 1: 32-63)

    // ldmatrix per-lane offsets (bytes)
    const uint32_t qoff = (uint32_t)(((wg * 16 + (lane & 15)) * 136 +
                                      ((lane >> 4) << 3)) * 2);
    const uint32_t koff0 = (uint32_t)(((h * 32 + (lane & 7)) * 136 +
                                       (((lane >> 3) & 1) << 3)) * 2);
    const uint32_t voff0 = (uint32_t)((h * 32 + (lane & 15)) * 136 * 2);
    const uint32_t loSel = (lane >> 4) ? (uint32_t)(T_HALF * 2) : 0u;  // hi->lo

    const float NEG = -1e30f;

    for (int pass = 0; pass < 2; pass++) {
        const int iq = pass ? (63 - blockIdx.x) : blockIdx.x;
        __syncthreads();   // previous pass fully done (incl. epilogue reads)

        // ---- load Q tile (hi/lo): 64 rows x 128 halves = 1024 uint4 each ----
        {
            const uint4* QH = (const uint4*)(g_Qh + ((size_t)b * SS + iq * 64) * DD);
            const uint4* QL = (const uint4*)(g_Ql + ((size_t)b * SS + iq * 64) * DD);
#pragma unroll
            for (int i = 0; i < 4; i++) {
                int idx = tid + i * 256;
                int r = idx >> 4, c = idx & 15;
                *(uint4*)(sQh + r * 136 + c * 8) = QH[idx];
                *(uint4*)(sQl + r * 136 + c * 8) = QL[idx];
            }
        }

        // ---- prefetch K/V tile 0 into stage 0 (1024 uint4 per array) ----
        {
            const size_t goff = ((size_t)b * SS) * DD;
            const uint4* srcs[4] = {(const uint4*)(g_Kh + goff), (const uint4*)(g_Kl + goff),
                                    (const uint4*)(g_Vh + goff), (const uint4*)(g_Vl + goff)};
#pragma unroll
            for (int a = 0; a < 4; a++)
#pragma unroll
                for (int i = 0; i < 4; i++) {
                    int idx = tid + i * 256;
                    int r = idx >> 4, c = idx & 15;
                    cp16(uKV + (uint32_t)(a * T_HALF * 2 + (r * 136 + c * 8) * 2),
                         srcs[a] + idx);
                }
            asm volatile("cp.async.commit_group;");
        }

        float o[16][4];
#pragma unroll
        for (int nd = 0; nd < 16; nd++)
#pragma unroll
            for (int k = 0; k < 4; k++) o[nd][k] = 0.0f;
        float mr0 = NEG, mr1 = NEG, lr0 = 0.0f, lr1 = 0.0f;

        for (int jt = 0; jt <= iq; jt++) {
            asm volatile("cp.async.wait_group 0;");
            __syncthreads();

            // prefetch next tile into the other stage
            if (jt < iq) {
                const int st = (jt + 1) & 1;
                const size_t goff = ((size_t)b * SS + (jt + 1) * 64) * DD;
                const uint4* srcs[4] = {(const uint4*)(g_Kh + goff), (const uint4*)(g_Kl + goff),
                                        (const uint4*)(g_Vh + goff), (const uint4*)(g_Vl + goff)};
                uint32_t sb = uKV + (uint32_t)(st * 4 * T_HALF * 2);
#pragma unroll
                for (int a = 0; a < 4; a++)
#pragma unroll
                    for (int i = 0; i < 4; i++) {
                        int idx = tid + i * 256;
                        int r = idx >> 4, c = idx & 15;
                        cp16(sb + (uint32_t)(a * T_HALF * 2 + (r * 136 + c * 8) * 2),
                             srcs[a] + idx);
                    }
                asm volatile("cp.async.commit_group;");
            }

            const uint32_t sb = uKV + (uint32_t)((jt & 1) * 4 * T_HALF * 2);
            const uint32_t kb = sb + koff0 + loSel;                    // Kh/Kl fused
            const uint32_t vb = sb + 2 * T_HALF * 2 + voff0 + loSel;   // Vh/Vl fused

            // ---- S half: 16 rows x 32 keys ----
            float c_[4][4];
#pragma unroll
            for (int nt = 0; nt < 4; nt++)
#pragma unroll
                for (int k = 0; k < 4; k++) c_[nt][k] = 0.0f;

#pragma unroll
            for (int ks = 0; ks < 8; ks++) {
                uint32_t qa[4], ql[4];
                ldsm_x4(qa, uQh + qoff + ks * 32);
                ldsm_x4(ql, uQl + qoff + ks * 32);
#pragma unroll
                for (int nt = 0; nt < 4; nt++) {
                    uint32_t kk[4];   // [0,1]=Khi, [2,3]=Klo
                    ldsm_x4(kk, kb + (uint32_t)(nt * 8 * 136 * 2 + ks * 32));
                    mma_bf16(c_[nt], qa, kk);
                    mma_bf16(c_[nt], qa, kk + 2);
                    mma_bf16(c_[nt], ql, kk);
                }
            }

            // ---- causal mask (diagonal tile only) ----
            if (jt == iq) {
                const int rl0 = wg * 16 + (lane >> 2);
                const int rl1 = rl0 + 8;
#pragma unroll
                for (int nt = 0; nt < 4; nt++) {
                    int cl = h * 32 + nt * 8 + (lane & 3) * 2;
                    if (cl > rl0) c_[nt][0] = NEG;
                    if (cl + 1 > rl0) c_[nt][1] = NEG;
                    if (cl > rl1) c_[nt][2] = NEG;
                    if (cl + 1 > rl1) c_[nt][3] = NEG;
                }
            }

            // ---- independent online softmax over this key half ----
            float mx0 = NEG, mx1 = NEG;
#pragma unroll
            for (int nt = 0; nt < 4; nt++) {
                mx0 = fmaxf(mx0, fmaxf(c_[nt][0], c_[nt][1]));
                mx1 = fmaxf(mx1, fmaxf(c_[nt][2], c_[nt][3]));
            }
            mx0 = fmaxf(mx0, __shfl_xor_sync(0xffffffffu, mx0, 1));
            mx0 = fmaxf(mx0, __shfl_xor_sync(0xffffffffu, mx0, 2));
            mx1 = fmaxf(mx1, __shfl_xor_sync(0xffffffffu, mx1, 1));
            mx1 = fmaxf(mx1, __shfl_xor_sync(0xffffffffu, mx1, 2));

            float nm0 = fmaxf(mr0, mx0), nm1 = fmaxf(mr1, mx1);
            float f0 = __expf(mr0 - nm0), f1 = __expf(mr1 - nm1);
            mr0 = nm0; mr1 = nm1;

            float rs0 = 0.0f, rs1 = 0.0f;
#pragma unroll
            for (int nt = 0; nt < 4; nt++) {
                c_[nt][0] = __expf(c_[nt][0] - nm0);
                c_[nt][1] = __expf(c_[nt][1] - nm0);
                c_[nt][2] = __expf(c_[nt][2] - nm1);
                c_[nt][3] = __expf(c_[nt][3] - nm1);
                rs0 += c_[nt][0] + c_[nt][1];
                rs1 += c_[nt][2] + c_[nt][3];
            }
            rs0 += __shfl_xor_sync(0xffffffffu, rs0, 1);
            rs0 += __shfl_xor_sync(0xffffffffu, rs0, 2);
            rs1 += __shfl_xor_sync(0xffffffffu, rs1, 1);
            rs1 += __shfl_xor_sync(0xffffffffu, rs1, 2);
            lr0 = lr0 * f0 + rs0;
            lr1 = lr1 * f1 + rs1;

#pragma unroll
            for (int nd = 0; nd < 16; nd++) {
                o[nd][0] *= f0; o[nd][1] *= f0;
                o[nd][2] *= f1; o[nd][3] *= f1;
            }

            // ---- O += P V over this key half (32 keys = 2 k-steps) ----
#pragma unroll
            for (int kp = 0; kp < 2; kp++) {
                uint32_t ph[4], pl[4];
                split_pack(c_[2 * kp][0],     c_[2 * kp][1],     ph[0], pl[0]);
                split_pack(c_[2 * kp][2],     c_[2 * kp][3],     ph[1], pl[1]);
                split_pack(c_[2 * kp + 1][0], c_[2 * kp + 1][1], ph[2], pl[2]);
                split_pack(c_[2 * kp + 1][2], c_[2 * kp + 1][3], ph[3], pl[3]);
#pragma unroll
                for (int nd = 0; nd < 16; nd++) {
                    uint32_t vv[4];   // [0,1]=Vhi, [2,3]=Vlo
                    ldsm_x4t(vv, vb + (uint32_t)(kp * 16 * 136 * 2 + nd * 16));
                    mma_bf16(o[nd], ph, vv);
                    mma_bf16(o[nd], ph, vv + 2);
                    mma_bf16(o[nd], pl, vv);
                }
            }
        }

        // ---- epilogue: merge the two key-half softmaxes, store ----
        __syncthreads();   // all compute done before overlaying stage-1 smem
        const int r0 = wg * 16 + (lane >> 2);
        const int cc = (lane & 3) * 2;
        if (h == 1) {
#pragma unroll
            for (int nd = 0; nd < 16; nd++) {
                *(float2*)(OB + r0 * 132 + nd * 8 + cc) = make_float2(o[nd][0], o[nd][1]);
                *(float2*)(OB + (r0 + 8) * 132 + nd * 8 + cc) = make_float2(o[nd][2], o[nd][3]);
            }
            if ((lane & 3) == 0) {
                mB[r0] = mr0; mB[r0 + 8] = mr1;
                lB[r0] = lr0; lB[r0 + 8] = lr1;
            }
        }
        __syncthreads();
        if (h == 0) {
            float mb0 = mB[r0], mb1 = mB[r0 + 8];
            float lb0 = lB[r0], lb1 = lB[r0 + 8];
            float m0 = fmaxf(mr0, mb0), m1 = fmaxf(mr1, mb1);
            float fa0 = __expf(mr0 - m0), fb0 = __expf(mb0 - m0);
            float fa1 = __expf(mr1 - m1), fb1 = __expf(mb1 - m1);
            float inv0 = 1.0f / (lr0 * fa0 + lb0 * fb0);
            float inv1 = 1.0f / (lr1 * fa1 + lb1 * fb1);

            const int rg0 = iq * 64 + r0;
            float* o0 = out + ((size_t)b * SS + rg0) * DD + cc;
            float* o1 = o0 + 8 * DD;
#pragma unroll
            for (int nd = 0; nd < 16; nd++) {
                float2 ob0 = *(float2*)(OB + r0 * 132 + nd * 8 + cc);
                float2 ob1 = *(float2*)(OB + (r0 + 8) * 132 + nd * 8 + cc);
                *(float2*)(o0 + nd * 8) =
                    make_float2((o[nd][0] * fa0 + ob0.x * fb0) * inv0,
                                (o[nd][1] * fa0 + ob0.y * fb0) * inv0);
                *(float2*)(o1 + nd * 8) =
                    make_float2((o[nd][2] * fa1 + ob1.x * fb1) * inv1,
                                (o[nd][3] * fa1 + ob1.y * fb1) * inv1);
            }
        }
    }
}

// ---------------------------------------------------------------------------
extern "C" void kernel_launch(void* const* d_in, const int* in_sizes, int n_in,
                              void* d_out, int out_size) {
    const float* x  = (const float*)d_in[0];
    const float* Wq = (const float*)d_in[1];
    const float* Wk = (const float*)d_in[2];
    const float* Wv = (const float*)d_in[3];
    float* out = (float*)d_out;

    cudaFuncSetAttribute(qkv_kernel, cudaFuncAttributeMaxDynamicSharedMemorySize, QKV_SMEM);
    cudaFuncSetAttribute(attn_kernel, cudaFuncAttributeMaxDynamicSharedMemorySize, ATTN_SMEM);

    qkv_kernel<<<dim3(BB * SS / 128, 3), 256, QKV_SMEM>>>(x, Wq, Wk, Wv);
    attn_kernel<<<dim3(32, BB), 256, ATTN_SMEM>>>(out);
}